// round 9
// baseline (speedup 1.0000x reference)
#include <cuda_runtime.h>
#include <cstdint>

#define T_STEPS 1024
#define NB 8192
#define NP 6
#define CHUNKS 32
#define CLEN (T_STEPS / CHUNKS)      // 32 steps per chunk
#define B1 8                         // scan batch (steps per pipeline stage)
#define NBT1 (T_STEPS / B1)          // 128 batches
#define STAGES 6                     // cp.async ring depth per scan warp
#define SCAN_BLOCKS 64               // 64 blocks x 128 thr = 8192 scan threads
#define CONS_PER_CHUNK 16            // 16 blocks x 512 basins = 8192
#define CONS_BLOCKS (CHUNKS * CONS_PER_CHUNK)          // 512
#define TOTAL_BLOCKS (SCAN_BLOCKS + CONS_BLOCKS)       // 576
#define SMEM_BYTES 122880            // 120 KB: 2 blocks can't share an SM -> 1 block/SM
#define RING_WARP_FLOATS (STAGES * 3 * B1 * 32)        // 4608 floats / warp

// checkpoint scratch + per-chunk ready counters
__device__ float g_ck_snow[CHUNKS * NB];
__device__ float g_ck_soil[CHUNKS * NB];
__device__ int   g_cnt[CHUNKS];

struct Params {
    float Qmax, Df, Tmax, Tmin, Smax, invSmax, posf_l2, c0;
};

__device__ __forceinline__ float ex2_approx(float x)
{
    float y;
    asm("ex2.approx.ftz.f32 %0, %1;" : "=f"(y) : "f"(x));
    return y;
}

__device__ __forceinline__ Params load_params(const float* __restrict__ sp, int b)
{
    const float lo[NP] = {0.0f, 100.0f, 10.0f, 0.0f, 0.0f, -3.0f};
    const float hi[NP] = {0.1f, 1500.0f, 50.0f, 5.0f, 3.0f, 0.0f};
    float prm[NP];
#pragma unroll
    for (int i = 0; i < NP; i++) {
        float x = sp[b * NP + i];
        float s = 1.0f / (1.0f + __expf(-x));
        prm[i] = lo[i] + (hi[i] - lo[i]) * s;
    }
    Params q;
    q.Smax = prm[1]; q.Qmax = prm[2]; q.Df = prm[3];
    q.Tmax = prm[4]; q.Tmin = prm[5];
    q.invSmax = 1.0f / prm[1];
    const float negf_l2 = -prm[0] * 1.4426950408889634f;   // -f*log2(e)
    q.posf_l2 = -negf_l2;
    q.c0 = negf_l2 * prm[1];                                // -f*log2(e)*Smax
    return q;
}

// one EXP-HYDRO step (MUST stay bit-identical between producer and consumer)
__device__ __forceinline__ void hydro_step(const Params& q,
                                           float p, float tm, float pe,
                                           float& snow, float& soil,
                                           float fx[8])
{
    const float snowfall    = (tm < q.Tmin) ? p : 0.0f;
    const float rainfall    = p - snowfall;
    const float melt        = fminf(snow, q.Df * fmaxf(tm - q.Tmax, 0.0f));
    const float evap        = pe * fminf(soil * q.invSmax, 1.0f);
    // Qmax * exp(-f*max(Smax-soil,0)) == Qmax * 2^min(c0 + posf_l2*soil, 0)
    const float baseflow    = q.Qmax * ex2_approx(fminf(fmaf(q.posf_l2, soil, q.c0), 0.0f));
    const float surfaceflow = fmaxf(soil - q.Smax, 0.0f);

    const float d_snow = snowfall - melt;
    const float d_soil = rainfall + melt - evap - baseflow - surfaceflow;

    snow = fmaxf(snow + d_snow, 1e-6f);
    soil = fmaxf(soil + d_soil, 1e-6f);

    fx[0] = snowfall; fx[1] = rainfall; fx[2] = melt; fx[3] = evap;
    fx[4] = baseflow; fx[5] = surfaceflow; fx[6] = d_snow; fx[7] = d_soil;
}

__device__ __forceinline__ void cpasync16(unsigned int dst_smem, const float* src)
{
    asm volatile("cp.async.cg.shared.global [%0], [%1], 16;"
                 :: "r"(dst_smem), "l"(src));
}
__device__ __forceinline__ void cp_commit()
{
    asm volatile("cp.async.commit_group;" ::: "memory");
}
template <int N>
__device__ __forceinline__ void cp_wait()
{
    asm volatile("cp.async.wait_group %0;" :: "n"(N) : "memory");
}
__device__ __forceinline__ int ld_acq(const int* p)
{
    int v;
    asm volatile("ld.acquire.gpu.global.s32 %0, [%1];" : "=r"(v) : "l"(p) : "memory");
    return v;
}

__global__ void zero_cnt_kernel()
{
    if (threadIdx.x < CHUNKS) g_cnt[threadIdx.x] = 0;
}

// fused: scan producers (bids 0..63, exclusive SMs) + fat consumers
__global__ void __launch_bounds__(128)
hydro_fused(const float* __restrict__ prcp,
            const float* __restrict__ temp,
            const float* __restrict__ pet,
            const float* __restrict__ sp,
            float* __restrict__ out)
{
    extern __shared__ float smem_dyn[];    // 120 KB requested -> 1 block/SM

    const int bid = blockIdx.x;
    const int tid = threadIdx.x;

    if (bid < SCAN_BLOCKS) {
        // ================= producer: serial state scan, 1 warp per SMSP ====
        const int w    = tid >> 5;
        const int lane = tid & 31;
        const int b    = bid * 128 + tid;
        const int wbase = bid * 128 + w * 32;
        const Params q = load_params(sp, b);

        float* wring = smem_dyn + w * RING_WARP_FLOATS;

        const float* vp0 = prcp + wbase;
        const float* vp1 = temp + wbase;
        const float* vp2 = pet  + wbase;

        // cooperative vectorized fill: 24 rows of 128B per batch -> 192 x 16B
        const int seg = lane & 7;
        const int r0  = lane >> 3;
        auto issue = [&](int batch, int s) {
            const int bc = (batch < NBT1) ? batch : NBT1 - 1;
            const size_t tbase = (size_t)bc * B1 * NB;
#pragma unroll
            for (int j = 0; j < 6; j++) {
                const int row = r0 + 4 * j;            // 0..23
                const int a   = row >> 3;              // forcing array
                const int i   = row & 7;               // step within batch
                const float* src = (a == 0 ? vp0 : (a == 1 ? vp1 : vp2))
                                 + tbase + (size_t)i * NB + seg * 4;
                unsigned int dst = (unsigned int)__cvta_generic_to_shared(
                    wring + ((s * 3 + a) * B1 + i) * 32 + seg * 4);
                cpasync16(dst, src);
            }
            cp_commit();
        };

#pragma unroll
        for (int s = 0; s < STAGES - 1; s++)
            issue(s, s);

        float snow = 0.0f, soil = 0.0f;
        float fx[8];

        for (int tb = 0; tb < NBT1; tb++) {
            issue(tb + STAGES - 1, (tb + STAGES - 1) % STAGES);
            cp_wait<STAGES - 1>();
            __syncwarp();

            if ((tb & 3) == 0) {
                const int c = tb >> 2;
                g_ck_snow[c * NB + b] = snow;
                g_ck_soil[c * NB + b] = soil;
                __threadfence();
                __syncwarp();
                if (lane == 0) atomicAdd(&g_cnt[c], 1);
                if (c == CHUNKS - 1) {
                    cp_wait<0>();
                    if (b < 0) g_ck_soil[b & 1] = fx[0] + fx[1] + fx[2] + fx[3]
                                                + fx[4] + fx[5] + fx[6] + fx[7];
                    return;
                }
            }

            const int s = tb % STAGES;
            const float* rs = wring + s * 3 * B1 * 32;
#pragma unroll
            for (int i = 0; i < B1; i++) {
                const float p  = rs[(0 * B1 + i) * 32 + lane];
                const float tm = rs[(1 * B1 + i) * 32 + lane];
                const float pe = rs[(2 * B1 + i) * 32 + lane];
                hydro_step(q, p, tm, pe, snow, soil, fx);
            }
        }
        if (b < 0) g_ck_soil[b & 1] = fx[0] + fx[1] + fx[2] + fx[3]
                                    + fx[4] + fx[5] + fx[6] + fx[7];
    } else {
        // ================= consumer: 4 basins/thread, float4 I/O ===========
        const int idx = bid - SCAN_BLOCKS;
        const int c   = idx >> 4;                    // chunk-major
        const int b0  = (idx & 15) * 512 + tid * 4;  // 4 consecutive basins

        Params qa[4];
#pragma unroll
        for (int k = 0; k < 4; k++) qa[k] = load_params(sp, b0 + k);

        const size_t t0 = (size_t)c * CLEN;
        const float* pp = prcp + t0 * NB + b0;
        const float* tp = temp + t0 * NB + b0;
        const float* ep = pet  + t0 * NB + b0;
        float*       o  = out  + t0 * (8 * NB) + b0;

        // prefetch first step BEFORE waiting (loads don't depend on checkpoint)
        float4 P = *reinterpret_cast<const float4*>(pp);
        float4 T = *reinterpret_cast<const float4*>(tp);
        float4 E = *reinterpret_cast<const float4*>(ep);

        // wait until all 256 scan warps published checkpoint c
        if (tid == 0) {
            while (ld_acq(&g_cnt[c]) < 256)
                __nanosleep(128);
        }
        __syncthreads();

        float4 sn4 = *reinterpret_cast<const float4*>(&g_ck_snow[c * NB + b0]);
        float4 so4 = *reinterpret_cast<const float4*>(&g_ck_soil[c * NB + b0]);
        float snow[4] = {sn4.x, sn4.y, sn4.z, sn4.w};
        float soil[4] = {so4.x, so4.y, so4.z, so4.w};

        for (int t = 0; t < CLEN; t++) {
            // 1-step register lookahead
            float4 Pn = P, Tn = T, En = E;
            if (t + 1 < CLEN) {
                const size_t off = (size_t)(t + 1) * NB;
                Pn = *reinterpret_cast<const float4*>(pp + off);
                Tn = *reinterpret_cast<const float4*>(tp + off);
                En = *reinterpret_cast<const float4*>(ep + off);
            }

            const float Pc[4] = {P.x, P.y, P.z, P.w};
            const float Tc[4] = {T.x, T.y, T.z, T.w};
            const float Ec[4] = {E.x, E.y, E.z, E.w};
            float fxk[4][8];
#pragma unroll
            for (int k = 0; k < 4; k++)
                hydro_step(qa[k], Pc[k], Tc[k], Ec[k], snow[k], soil[k], fxk[k]);

#pragma unroll
            for (int f = 0; f < 8; f++) {
                float4 v = make_float4(fxk[0][f], fxk[1][f], fxk[2][f], fxk[3][f]);
                __stcs(reinterpret_cast<float4*>(o + f * NB), v);
            }
            o += 8 * NB;
            P = Pn; T = Tn; E = En;
        }
    }
}

extern "C" void kernel_launch(void* const* d_in, const int* in_sizes, int n_in,
                              void* d_out, int out_size)
{
    const float* prcp = (const float*)d_in[0];
    const float* temp = (const float*)d_in[1];
    const float* pet  = (const float*)d_in[2];
    const float* sp   = (const float*)d_in[3];
    float* out = (float*)d_out;

    // opt in to 120 KB dynamic smem (idempotent host call, capture-safe)
    cudaFuncSetAttribute(hydro_fused,
                         cudaFuncAttributeMaxDynamicSharedMemorySize, SMEM_BYTES);

    zero_cnt_kernel<<<1, 32>>>();
    hydro_fused<<<TOTAL_BLOCKS, 128, SMEM_BYTES>>>(prcp, temp, pet, sp, out);
}

// round 10
// speedup vs baseline: 1.2097x; 1.2097x over previous
#include <cuda_runtime.h>
#include <cstdint>

#define T_STEPS 1024
#define NB 8192
#define NP 6
#define CHUNKS 32
#define CLEN (T_STEPS / CHUNKS)      // 32 steps per chunk
#define B1 8                         // scan batch (steps per pipeline stage)
#define NBT1 (T_STEPS / B1)          // 128 batches
#define STAGES 6                     // cp.async ring depth per scan warp
#define SCAN_BLOCKS 64               // 64 blocks x 128 active thr = 8192 scan threads
#define CONS_PER_CHUNK 4             // 4 blocks x 512 thr x 4 basins = 8192
#define CONS_BLOCKS (CHUNKS * CONS_PER_CHUNK)          // 128
#define TOTAL_BLOCKS (SCAN_BLOCKS + CONS_BLOCKS)       // 192
#define SMEM_BYTES 122880            // 120 KB: forces 1 block/SM
#define RING_WARP_FLOATS (STAGES * 3 * B1 * 32)        // 4608 floats / warp (73.7 KB total)

// checkpoint scratch + per-chunk ready counters
__device__ float g_ck_snow[CHUNKS * NB];
__device__ float g_ck_soil[CHUNKS * NB];
__device__ int   g_cnt[CHUNKS];

struct Params {
    float Qmax, Df, Tmax, Tmin, Smax, invSmax, posf_l2, c0;
};

__device__ __forceinline__ float ex2_approx(float x)
{
    float y;
    asm("ex2.approx.ftz.f32 %0, %1;" : "=f"(y) : "f"(x));
    return y;
}

__device__ __forceinline__ Params load_params(const float* __restrict__ sp, int b)
{
    const float lo[NP] = {0.0f, 100.0f, 10.0f, 0.0f, 0.0f, -3.0f};
    const float hi[NP] = {0.1f, 1500.0f, 50.0f, 5.0f, 3.0f, 0.0f};
    float prm[NP];
#pragma unroll
    for (int i = 0; i < NP; i++) {
        float x = sp[b * NP + i];
        float s = 1.0f / (1.0f + __expf(-x));
        prm[i] = lo[i] + (hi[i] - lo[i]) * s;
    }
    Params q;
    q.Smax = prm[1]; q.Qmax = prm[2]; q.Df = prm[3];
    q.Tmax = prm[4]; q.Tmin = prm[5];
    q.invSmax = 1.0f / prm[1];
    const float negf_l2 = -prm[0] * 1.4426950408889634f;   // -f*log2(e)
    q.posf_l2 = -negf_l2;
    q.c0 = negf_l2 * prm[1];                                // -f*log2(e)*Smax
    return q;
}

// one EXP-HYDRO step (MUST stay bit-identical between producer and consumer)
__device__ __forceinline__ void hydro_step(const Params& q,
                                           float p, float tm, float pe,
                                           float& snow, float& soil,
                                           float fx[8])
{
    const float snowfall    = (tm < q.Tmin) ? p : 0.0f;
    const float rainfall    = p - snowfall;
    const float melt        = fminf(snow, q.Df * fmaxf(tm - q.Tmax, 0.0f));
    const float evap        = pe * fminf(soil * q.invSmax, 1.0f);
    const float baseflow    = q.Qmax * ex2_approx(fminf(fmaf(q.posf_l2, soil, q.c0), 0.0f));
    const float surfaceflow = fmaxf(soil - q.Smax, 0.0f);

    const float d_snow = snowfall - melt;
    const float d_soil = rainfall + melt - evap - baseflow - surfaceflow;

    snow = fmaxf(snow + d_snow, 1e-6f);
    soil = fmaxf(soil + d_soil, 1e-6f);

    fx[0] = snowfall; fx[1] = rainfall; fx[2] = melt; fx[3] = evap;
    fx[4] = baseflow; fx[5] = surfaceflow; fx[6] = d_snow; fx[7] = d_soil;
}

__device__ __forceinline__ void cpasync16(unsigned int dst_smem, const float* src)
{
    asm volatile("cp.async.cg.shared.global [%0], [%1], 16;"
                 :: "r"(dst_smem), "l"(src));
}
__device__ __forceinline__ void cp_commit()
{
    asm volatile("cp.async.commit_group;" ::: "memory");
}
template <int N>
__device__ __forceinline__ void cp_wait()
{
    asm volatile("cp.async.wait_group %0;" :: "n"(N) : "memory");
}
__device__ __forceinline__ int ld_acq(const int* p)
{
    int v;
    asm volatile("ld.acquire.gpu.global.s32 %0, [%1];" : "=r"(v) : "l"(p) : "memory");
    return v;
}

__global__ void zero_cnt_kernel()
{
    if (threadIdx.x < CHUNKS) g_cnt[threadIdx.x] = 0;
}

// fused: scan producers (bids 0..63, exclusive SMs) + fat consumers (512 thr)
__global__ void __launch_bounds__(512)
hydro_fused(const float* __restrict__ prcp,
            const float* __restrict__ temp,
            const float* __restrict__ pet,
            const float* __restrict__ sp,
            float* __restrict__ out)
{
    extern __shared__ float smem_dyn[];    // 120 KB requested -> 1 block/SM

    const int bid = blockIdx.x;
    const int tid = threadIdx.x;

    if (bid < SCAN_BLOCKS) {
        // ================= producer: serial state scan, 4 warps own the SM =
        if (tid >= 128) return;            // free 12 warps; scan warps keep SM exclusive

        const int w    = tid >> 5;
        const int lane = tid & 31;
        const int b    = bid * 128 + tid;
        const int wbase = bid * 128 + w * 32;
        const Params q = load_params(sp, b);

        float* wring = smem_dyn + w * RING_WARP_FLOATS;

        const float* vp0 = prcp + wbase;
        const float* vp1 = temp + wbase;
        const float* vp2 = pet  + wbase;

        // cooperative vectorized fill: 24 rows of 128B per batch -> 192 x 16B
        const int seg = lane & 7;
        const int r0  = lane >> 3;
        auto issue = [&](int batch, int s) {
            const int bc = (batch < NBT1) ? batch : NBT1 - 1;
            const size_t tbase = (size_t)bc * B1 * NB;
#pragma unroll
            for (int j = 0; j < 6; j++) {
                const int row = r0 + 4 * j;            // 0..23
                const int a   = row >> 3;              // forcing array
                const int i   = row & 7;               // step within batch
                const float* src = (a == 0 ? vp0 : (a == 1 ? vp1 : vp2))
                                 + tbase + (size_t)i * NB + seg * 4;
                unsigned int dst = (unsigned int)__cvta_generic_to_shared(
                    wring + ((s * 3 + a) * B1 + i) * 32 + seg * 4);
                cpasync16(dst, src);
            }
            cp_commit();
        };

#pragma unroll
        for (int s = 0; s < STAGES - 1; s++)
            issue(s, s);

        float snow = 0.0f, soil = 0.0f;
        float fx[8];

        for (int tb = 0; tb < NBT1; tb++) {
            issue(tb + STAGES - 1, (tb + STAGES - 1) % STAGES);
            cp_wait<STAGES - 1>();
            __syncwarp();

            if ((tb & 3) == 0) {
                const int c = tb >> 2;
                g_ck_snow[c * NB + b] = snow;
                g_ck_soil[c * NB + b] = soil;
                __threadfence();
                __syncwarp();
                if (lane == 0) atomicAdd(&g_cnt[c], 1);
                if (c == CHUNKS - 1) {
                    cp_wait<0>();
                    if (b < 0) g_ck_soil[b & 1] = fx[0] + fx[1] + fx[2] + fx[3]
                                                + fx[4] + fx[5] + fx[6] + fx[7];
                    return;
                }
            }

            const int s = tb % STAGES;
            const float* rs = wring + s * 3 * B1 * 32;
#pragma unroll
            for (int i = 0; i < B1; i++) {
                const float p  = rs[(0 * B1 + i) * 32 + lane];
                const float tm = rs[(1 * B1 + i) * 32 + lane];
                const float pe = rs[(2 * B1 + i) * 32 + lane];
                hydro_step(q, p, tm, pe, snow, soil, fx);
            }
        }
        if (b < 0) g_ck_soil[b & 1] = fx[0] + fx[1] + fx[2] + fx[3]
                                    + fx[4] + fx[5] + fx[6] + fx[7];
    } else {
        // ================= consumer: 512 thr x 4 basins, float4 I/O ========
        const int idx = bid - SCAN_BLOCKS;
        const int c   = idx >> 2;                      // chunk-major
        const int b0  = (idx & 3) * 2048 + tid * 4;    // 4 consecutive basins

        Params qa[4];
#pragma unroll
        for (int k = 0; k < 4; k++) qa[k] = load_params(sp, b0 + k);

        const size_t t0 = (size_t)c * CLEN;
        const float* pp = prcp + t0 * NB + b0;
        const float* tp = temp + t0 * NB + b0;
        const float* ep = pet  + t0 * NB + b0;
        float*       o  = out  + t0 * (8 * NB) + b0;

        // prefetch first step BEFORE waiting (loads don't depend on checkpoint)
        float4 P = *reinterpret_cast<const float4*>(pp);
        float4 T = *reinterpret_cast<const float4*>(tp);
        float4 E = *reinterpret_cast<const float4*>(ep);

        // wait until all 256 scan warps published checkpoint c
        if (tid == 0) {
            while (ld_acq(&g_cnt[c]) < 256)
                __nanosleep(128);
        }
        __syncthreads();

        float4 sn4 = *reinterpret_cast<const float4*>(&g_ck_snow[c * NB + b0]);
        float4 so4 = *reinterpret_cast<const float4*>(&g_ck_soil[c * NB + b0]);
        float snow[4] = {sn4.x, sn4.y, sn4.z, sn4.w};
        float soil[4] = {so4.x, so4.y, so4.z, so4.w};

        for (int t = 0; t < CLEN; t++) {
            // 1-step register lookahead
            float4 Pn = P, Tn = T, En = E;
            if (t + 1 < CLEN) {
                const size_t off = (size_t)(t + 1) * NB;
                Pn = *reinterpret_cast<const float4*>(pp + off);
                Tn = *reinterpret_cast<const float4*>(tp + off);
                En = *reinterpret_cast<const float4*>(ep + off);
            }

            const float Pc[4] = {P.x, P.y, P.z, P.w};
            const float Tc[4] = {T.x, T.y, T.z, T.w};
            const float Ec[4] = {E.x, E.y, E.z, E.w};
            float fxk[4][8];
#pragma unroll
            for (int k = 0; k < 4; k++)
                hydro_step(qa[k], Pc[k], Tc[k], Ec[k], snow[k], soil[k], fxk[k]);

#pragma unroll
            for (int f = 0; f < 8; f++) {
                float4 v = make_float4(fxk[0][f], fxk[1][f], fxk[2][f], fxk[3][f]);
                __stcs(reinterpret_cast<float4*>(o + f * NB), v);
            }
            o += 8 * NB;
            P = Pn; T = Tn; E = En;
        }
    }
}

extern "C" void kernel_launch(void* const* d_in, const int* in_sizes, int n_in,
                              void* d_out, int out_size)
{
    const float* prcp = (const float*)d_in[0];
    const float* temp = (const float*)d_in[1];
    const float* pet  = (const float*)d_in[2];
    const float* sp   = (const float*)d_in[3];
    float* out = (float*)d_out;

    cudaFuncSetAttribute(hydro_fused,
                         cudaFuncAttributeMaxDynamicSharedMemorySize, SMEM_BYTES);

    zero_cnt_kernel<<<1, 32>>>();
    hydro_fused<<<TOTAL_BLOCKS, 512, SMEM_BYTES>>>(prcp, temp, pet, sp, out);
}

// round 11
// speedup vs baseline: 1.4886x; 1.2305x over previous
#include <cuda_runtime.h>
#include <cstdint>

#define T_STEPS 1024
#define NB 8192
#define NP 6
#define CHUNKS 32
#define CLEN (T_STEPS / CHUNKS)      // 32 steps per chunk
#define B1 8                         // scan batch (steps per pipeline stage)
#define NBT1 (T_STEPS / B1)          // 128 batches
#define STAGES 8                     // cp.async ring depth per scan warp
#define B2 4                         // pass-2 register batch
#define NBT2 (CLEN / B2)             // 8 batches per chunk
#define SMEM_BYTES 122880            // 120 KB: forces 1 scan block per SM
#define RING_WARP_FLOATS (STAGES * 3 * B1 * 32)   // 6144 floats = 24 KB/warp, 96 KB/block

// checkpoint scratch: state at the START of each chunk (2 MB -> L2 resident)
__device__ float g_ck_snow[CHUNKS * NB];
__device__ float g_ck_soil[CHUNKS * NB];

struct Params {
    float Qmax, Df, Tmax, Tmin, Smax, invSmax, posf_l2, c0;
};

__device__ __forceinline__ float ex2_approx(float x)
{
    float y;
    asm("ex2.approx.ftz.f32 %0, %1;" : "=f"(y) : "f"(x));
    return y;
}

__device__ __forceinline__ Params load_params(const float* __restrict__ sp, int b)
{
    const float lo[NP] = {0.0f, 100.0f, 10.0f, 0.0f, 0.0f, -3.0f};
    const float hi[NP] = {0.1f, 1500.0f, 50.0f, 5.0f, 3.0f, 0.0f};
    float prm[NP];
#pragma unroll
    for (int i = 0; i < NP; i++) {
        float x = sp[b * NP + i];
        float s = 1.0f / (1.0f + __expf(-x));
        prm[i] = lo[i] + (hi[i] - lo[i]) * s;
    }
    Params q;
    q.Smax = prm[1]; q.Qmax = prm[2]; q.Df = prm[3];
    q.Tmax = prm[4]; q.Tmin = prm[5];
    q.invSmax = 1.0f / prm[1];
    const float negf_l2 = -prm[0] * 1.4426950408889634f;   // -f*log2(e)
    q.posf_l2 = -negf_l2;
    q.c0 = negf_l2 * prm[1];                                // -f*log2(e)*Smax
    return q;
}

// one EXP-HYDRO step (MUST stay bit-identical between scan and pass2)
__device__ __forceinline__ void hydro_step(const Params& q,
                                           float p, float tm, float pe,
                                           float& snow, float& soil,
                                           float fx[8])
{
    const float snowfall    = (tm < q.Tmin) ? p : 0.0f;
    const float rainfall    = p - snowfall;
    const float melt        = fminf(snow, q.Df * fmaxf(tm - q.Tmax, 0.0f));
    const float evap        = pe * fminf(soil * q.invSmax, 1.0f);
    // Qmax * exp(-f*max(Smax-soil,0)) == Qmax * 2^min(c0 + posf_l2*soil, 0)
    const float baseflow    = q.Qmax * ex2_approx(fminf(fmaf(q.posf_l2, soil, q.c0), 0.0f));
    const float surfaceflow = fmaxf(soil - q.Smax, 0.0f);

    const float d_snow = snowfall - melt;
    const float d_soil = rainfall + melt - evap - baseflow - surfaceflow;

    snow = fmaxf(snow + d_snow, 1e-6f);
    soil = fmaxf(soil + d_soil, 1e-6f);

    fx[0] = snowfall; fx[1] = rainfall; fx[2] = melt; fx[3] = evap;
    fx[4] = baseflow; fx[5] = surfaceflow; fx[6] = d_snow; fx[7] = d_soil;
}

__device__ __forceinline__ void cpasync16(unsigned int dst_smem, const float* src)
{
    asm volatile("cp.async.cg.shared.global [%0], [%1], 16;"
                 :: "r"(dst_smem), "l"(src));
}
__device__ __forceinline__ void cp_commit()
{
    asm volatile("cp.async.commit_group;" ::: "memory");
}
template <int N>
__device__ __forceinline__ void cp_wait()
{
    asm volatile("cp.async.wait_group %0;" :: "n"(N) : "memory");
}

// ---------------- pass 1: serial state scan, exclusive SMs, deep ring -------
__global__ void __launch_bounds__(128)
hydro_scan(const float* __restrict__ prcp,
           const float* __restrict__ temp,
           const float* __restrict__ pet,
           const float* __restrict__ sp)
{
    extern __shared__ float smem_dyn[];    // 120 KB requested -> 1 block/SM

    const int tid  = threadIdx.x;
    const int w    = tid >> 5;
    const int lane = tid & 31;
    const int b    = blockIdx.x * 128 + tid;
    const int wbase = blockIdx.x * 128 + w * 32;
    const Params q = load_params(sp, b);

    float* wring = smem_dyn + w * RING_WARP_FLOATS;

    const float* vp0 = prcp + wbase;
    const float* vp1 = temp + wbase;
    const float* vp2 = pet  + wbase;

    // cooperative vectorized fill: 24 rows of 128B per batch -> 192 x 16B
    // lane l handles seg = l&7, rows (l>>3)+4j, j=0..5
    const int seg = lane & 7;
    const int r0  = lane >> 3;
    auto issue = [&](int batch, int s) {
        const int bc = (batch < NBT1) ? batch : NBT1 - 1;
        const size_t tbase = (size_t)bc * B1 * NB;
#pragma unroll
        for (int j = 0; j < 6; j++) {
            const int row = r0 + 4 * j;            // 0..23
            const int a   = row >> 3;              // forcing array
            const int i   = row & 7;               // step within batch
            const float* src = (a == 0 ? vp0 : (a == 1 ? vp1 : vp2))
                             + tbase + (size_t)i * NB + seg * 4;
            unsigned int dst = (unsigned int)__cvta_generic_to_shared(
                wring + ((s * 3 + a) * B1 + i) * 32 + seg * 4);
            cpasync16(dst, src);
        }
        cp_commit();
    };

#pragma unroll
    for (int s = 0; s < STAGES - 1; s++)
        issue(s, s);

    float snow = 0.0f, soil = 0.0f;
    float fx[8];

    for (int tb = 0; tb < NBT1; tb++) {
        issue(tb + STAGES - 1, (tb + STAGES - 1) % STAGES);
        cp_wait<STAGES - 1>();
        __syncwarp();

        // chunk boundary: CLEN=32 steps = 4 batches
        if ((tb & 3) == 0) {
            const int c = tb >> 2;
            g_ck_snow[c * NB + b] = snow;
            g_ck_soil[c * NB + b] = soil;
            if (c == CHUNKS - 1) {
                // last checkpoint written: remaining state evolution is dead work
                cp_wait<0>();
                if (b < 0) g_ck_soil[b & 1] = fx[0] + fx[1] + fx[2] + fx[3]
                                            + fx[4] + fx[5] + fx[6] + fx[7];
                return;
            }
        }

        const int s = tb % STAGES;
        const float* rs = wring + s * 3 * B1 * 32;
#pragma unroll
        for (int i = 0; i < B1; i++) {
            const float p  = rs[(0 * B1 + i) * 32 + lane];
            const float tm = rs[(1 * B1 + i) * 32 + lane];
            const float pe = rs[(2 * B1 + i) * 32 + lane];
            hydro_step(q, p, tm, pe, snow, soil, fx);
        }
    }
    if (b < 0) g_ck_soil[b & 1] = fx[0] + fx[1] + fx[2] + fx[3]
                                + fx[4] + fx[5] + fx[6] + fx[7];
}

// ---------------- pass 2: parallel chunks from checkpoints (R4 proven) ------
__global__ void __launch_bounds__(128)
hydro_pass2(const float* __restrict__ prcp,
            const float* __restrict__ temp,
            const float* __restrict__ pet,
            const float* __restrict__ sp,
            float* __restrict__ out)
{
    const int b = blockIdx.x * 128 + threadIdx.x;
    const int c = blockIdx.y;
    const Params q = load_params(sp, b);

    float snow = g_ck_snow[c * NB + b];
    float soil = g_ck_soil[c * NB + b];

    const size_t t0 = (size_t)c * CLEN;
    const float* pp = prcp + t0 * NB + b;
    const float* tp = temp + t0 * NB + b;
    const float* ep = pet  + t0 * NB + b;
    float*       o  = out  + t0 * (8 * NB) + b;

    float PA[B2], TA[B2], EA[B2];
    float PB[B2], TB[B2], EB[B2];
    float fx[8];

#pragma unroll
    for (int i = 0; i < B2; i++) {
        PA[i] = pp[i * NB]; TA[i] = tp[i * NB]; EA[i] = ep[i * NB];
    }

    for (int tb = 0; tb < NBT2; tb += 2) {
        {
            const size_t base = (size_t)(tb + 1) * B2 * NB;
#pragma unroll
            for (int i = 0; i < B2; i++) {
                PB[i] = pp[base + i * NB]; TB[i] = tp[base + i * NB]; EB[i] = ep[base + i * NB];
            }
        }
#pragma unroll
        for (int i = 0; i < B2; i++) {
            hydro_step(q, PA[i], TA[i], EA[i], snow, soil, fx);
            __stcs(o + 0 * NB, fx[0]); __stcs(o + 1 * NB, fx[1]);
            __stcs(o + 2 * NB, fx[2]); __stcs(o + 3 * NB, fx[3]);
            __stcs(o + 4 * NB, fx[4]); __stcs(o + 5 * NB, fx[5]);
            __stcs(o + 6 * NB, fx[6]); __stcs(o + 7 * NB, fx[7]);
            o += 8 * NB;
        }
        if (tb + 2 < NBT2) {
            const size_t base = (size_t)(tb + 2) * B2 * NB;
#pragma unroll
            for (int i = 0; i < B2; i++) {
                PA[i] = pp[base + i * NB]; TA[i] = tp[base + i * NB]; EA[i] = ep[base + i * NB];
            }
        }
#pragma unroll
        for (int i = 0; i < B2; i++) {
            hydro_step(q, PB[i], TB[i], EB[i], snow, soil, fx);
            __stcs(o + 0 * NB, fx[0]); __stcs(o + 1 * NB, fx[1]);
            __stcs(o + 2 * NB, fx[2]); __stcs(o + 3 * NB, fx[3]);
            __stcs(o + 4 * NB, fx[4]); __stcs(o + 5 * NB, fx[5]);
            __stcs(o + 6 * NB, fx[6]); __stcs(o + 7 * NB, fx[7]);
            o += 8 * NB;
        }
    }
}

extern "C" void kernel_launch(void* const* d_in, const int* in_sizes, int n_in,
                              void* d_out, int out_size)
{
    const float* prcp = (const float*)d_in[0];
    const float* temp = (const float*)d_in[1];
    const float* pet  = (const float*)d_in[2];
    const float* sp   = (const float*)d_in[3];
    float* out = (float*)d_out;

    cudaFuncSetAttribute(hydro_scan,
                         cudaFuncAttributeMaxDynamicSharedMemorySize, SMEM_BYTES);

    // pass 1: 64 blocks x 128 thr, 1 block/SM (120 KB smem), deep cp.async ring
    hydro_scan<<<64, 128, SMEM_BYTES>>>(prcp, temp, pet, sp);
    // pass 2: 32 chunks x 64 blocks x 128 threads = 8192 warps (R4 proven config)
    dim3 grid2(NB / 128, CHUNKS);
    hydro_pass2<<<grid2, 128>>>(prcp, temp, pet, sp, out);
}

// round 12
// speedup vs baseline: 2.2395x; 1.5045x over previous
#include <cuda_runtime.h>
#include <cstdint>

#define T_STEPS 1024
#define NB 8192
#define NP 6
#define B1 8                         // batch (steps per pipeline stage)
#define NBT1 (T_STEPS / B1)          // 128 batches
#define STAGES 8                     // cp.async ring depth per warp
#define SMEM_BYTES 122880            // 120 KB: forces 1 block per SM
#define RING_WARP_FLOATS (STAGES * 3 * B1 * 32)   // 6144 floats = 24 KB/warp

struct Params {
    float Qmax, Df, Tmax, Tmin, Smax, invSmax, posf_l2, c0;
};

__device__ __forceinline__ float ex2_approx(float x)
{
    float y;
    asm("ex2.approx.ftz.f32 %0, %1;" : "=f"(y) : "f"(x));
    return y;
}

__device__ __forceinline__ Params load_params(const float* __restrict__ sp, int b)
{
    const float lo[NP] = {0.0f, 100.0f, 10.0f, 0.0f, 0.0f, -3.0f};
    const float hi[NP] = {0.1f, 1500.0f, 50.0f, 5.0f, 3.0f, 0.0f};
    float prm[NP];
#pragma unroll
    for (int i = 0; i < NP; i++) {
        float x = sp[b * NP + i];
        float s = 1.0f / (1.0f + __expf(-x));
        prm[i] = lo[i] + (hi[i] - lo[i]) * s;
    }
    Params q;
    q.Smax = prm[1]; q.Qmax = prm[2]; q.Df = prm[3];
    q.Tmax = prm[4]; q.Tmin = prm[5];
    q.invSmax = 1.0f / prm[1];
    const float negf_l2 = -prm[0] * 1.4426950408889634f;   // -f*log2(e)
    q.posf_l2 = -negf_l2;
    q.c0 = negf_l2 * prm[1];                                // -f*log2(e)*Smax
    return q;
}

__device__ __forceinline__ void cpasync16(unsigned int dst_smem, const float* src)
{
    asm volatile("cp.async.cg.shared.global [%0], [%1], 16;"
                 :: "r"(dst_smem), "l"(src));
}
__device__ __forceinline__ void cp_commit()
{
    asm volatile("cp.async.commit_group;" ::: "memory");
}
template <int N>
__device__ __forceinline__ void cp_wait()
{
    asm volatile("cp.async.wait_group %0;" :: "n"(N) : "memory");
}

// single pass: serial state scan that stores all fluxes directly.
// 128 blocks x 64 threads, 120 KB dynamic smem -> 1 block/SM,
// 2 warps/SM each on its own SMSP; cp.async ring feeds the forcings.
__global__ void __launch_bounds__(64)
hydro_direct(const float* __restrict__ prcp,
             const float* __restrict__ temp,
             const float* __restrict__ pet,
             const float* __restrict__ sp,
             float* __restrict__ out)
{
    extern __shared__ float smem_dyn[];

    const int tid   = threadIdx.x;
    const int w     = tid >> 5;
    const int lane  = tid & 31;
    const int b     = blockIdx.x * 64 + tid;
    const int wbase = blockIdx.x * 64 + w * 32;
    const Params q  = load_params(sp, b);

    float* wring = smem_dyn + w * RING_WARP_FLOATS;

    const float* vp0 = prcp + wbase;
    const float* vp1 = temp + wbase;
    const float* vp2 = pet  + wbase;

    // cooperative vectorized fill: 24 rows of 128B per batch -> 192 x 16B
    // lane l handles seg = l&7, rows (l>>3)+4j, j=0..5
    const int seg = lane & 7;
    const int r0  = lane >> 3;
    auto issue = [&](int batch, int s) {
        const int bc = (batch < NBT1) ? batch : NBT1 - 1;
        const size_t tbase = (size_t)bc * B1 * NB;
#pragma unroll
        for (int j = 0; j < 6; j++) {
            const int row = r0 + 4 * j;            // 0..23
            const int a   = row >> 3;              // forcing array
            const int i   = row & 7;               // step within batch
            const float* src = (a == 0 ? vp0 : (a == 1 ? vp1 : vp2))
                             + tbase + (size_t)i * NB + seg * 4;
            unsigned int dst = (unsigned int)__cvta_generic_to_shared(
                wring + ((s * 3 + a) * B1 + i) * 32 + seg * 4);
            cpasync16(dst, src);
        }
        cp_commit();
    };

#pragma unroll
    for (int s = 0; s < STAGES - 1; s++)
        issue(s, s);

    float snow = 0.0f, soil = 0.0f;
    float* o = out + b;                 // [T, 8, B] walk

    for (int tb = 0; tb < NBT1; tb++) {
        issue(tb + STAGES - 1, (tb + STAGES - 1) % STAGES);
        cp_wait<STAGES - 1>();
        __syncwarp();

        const int s = tb % STAGES;
        const float* rs = wring + s * 3 * B1 * 32;
#pragma unroll
        for (int i = 0; i < B1; i++) {
            const float p  = rs[(0 * B1 + i) * 32 + lane];
            const float tm = rs[(1 * B1 + i) * 32 + lane];
            const float pe = rs[(2 * B1 + i) * 32 + lane];

            const float snowfall    = (tm < q.Tmin) ? p : 0.0f;
            const float rainfall    = p - snowfall;
            const float melt        = fminf(snow, q.Df * fmaxf(tm - q.Tmax, 0.0f));
            const float evap        = pe * fminf(soil * q.invSmax, 1.0f);
            const float baseflow    = q.Qmax *
                ex2_approx(fminf(fmaf(q.posf_l2, soil, q.c0), 0.0f));
            const float surfaceflow = fmaxf(soil - q.Smax, 0.0f);

            const float d_snow = snowfall - melt;
            const float d_soil = rainfall + melt - evap - baseflow - surfaceflow;

            snow = fmaxf(snow + d_snow, 1e-6f);
            soil = fmaxf(soil + d_soil, 1e-6f);

            // stream the 8 fluxes straight to GMEM
            __stcs(o + 0 * NB, snowfall);
            __stcs(o + 1 * NB, rainfall);
            __stcs(o + 2 * NB, melt);
            __stcs(o + 3 * NB, evap);
            __stcs(o + 4 * NB, baseflow);
            __stcs(o + 5 * NB, surfaceflow);
            __stcs(o + 6 * NB, d_snow);
            __stcs(o + 7 * NB, d_soil);
            o += 8 * NB;
        }
    }
}

extern "C" void kernel_launch(void* const* d_in, const int* in_sizes, int n_in,
                              void* d_out, int out_size)
{
    const float* prcp = (const float*)d_in[0];
    const float* temp = (const float*)d_in[1];
    const float* pet  = (const float*)d_in[2];
    const float* sp   = (const float*)d_in[3];
    float* out = (float*)d_out;

    cudaFuncSetAttribute(hydro_direct,
                         cudaFuncAttributeMaxDynamicSharedMemorySize, SMEM_BYTES);

    // 128 blocks x 64 threads: 1 block/SM (120 KB smem), 2 warps/SM,
    // 256 serial-chain warps each owning an SMSP, stores spread over 128 SMs.
    hydro_direct<<<128, 64, SMEM_BYTES>>>(prcp, temp, pet, sp, out);
}